// round 14
// baseline (speedup 1.0000x reference)
#include <cuda_runtime.h>
#include <cuda_bf16.h>

static constexpr int THREADS       = 256;                 // 8 warps/block
static constexpr int WARPS_PER_BLK = THREADS / 32;
static constexpr int BLOCKS_PER_SM = 5;                   // smem-limited (43KB/block)
static constexpr int WAVE_BLOCKS   = 148 * BLOCKS_PER_SM; // 740
static constexpr int STAGES        = 6;
static constexpr int CHUNK_ROWS    = 32;                  // per warp-chunk
static constexpr int IN_B          = CHUNK_ROWS * 12;     // 384
static constexpr int TG_B          = CHUNK_ROWS * 12;     // 384
static constexpr int CS_B          = CHUNK_ROWS * 4;      // 128
static constexpr int STAGE_B       = IN_B + TG_B + CS_B;  // 896

__device__ double        g_part[1184];
__device__ unsigned int  g_ticket = 0;   // self-resetting, graph-replay safe

__device__ __forceinline__ void cp16(void* smem_dst, const void* gmem_src) {
    unsigned int sa = (unsigned int)__cvta_generic_to_shared(smem_dst);
    asm volatile("cp.async.cg.shared.global [%0], [%1], 16;" :: "r"(sa), "l"(gmem_src));
}
__device__ __forceinline__ void cp_commit() {
    asm volatile("cp.async.commit_group;");
}
__device__ __forceinline__ void cp_wait4() {
    asm volatile("cp.async.wait_group 4;");   // STAGES-2
}
__device__ __forceinline__ void cp_wait0() {
    asm volatile("cp.async.wait_group 0;");
}

__device__ __forceinline__ float row_term(float i0, float i1, float i2,
                                          int t0, int t1, int t2, int cs,
                                          const float* __restrict__ w,
                                          float invB) {
    float sw = w[t2 / 100 - 1];                 // class {100..700} -> idx
    float f0 = (float)t0, f1 = (float)t1, f2 = (float)t2;
    float d0 = i0 - f0, d1 = i1 - f1, d2 = i2 - f2;
    // sensors .mean(axis=1) -> 0.5*(d0^2+d1^2); anomaly -> d2^2; /B via invB
    float main_t = sw * (0.5f * (d0 * d0 + d1 * d1) + d2 * d2);

    // R02: lo = 6400 (state 4), 6000 (states 5-8), else 11500 ; hi = 12000
    float r02lo = (cs == 4) ? 6400.0f
                 : ((unsigned)(cs - 5) <= 3u ? 6000.0f : 11500.0f);
    // R03: lo = 2200 ; hi = 13000 (state 8) else 2500
    float r03hi = (cs == 8) ? 13000.0f : 2500.0f;

    float b0 = fminf(f0 - r02lo, 0.0f);
    float a0 = fmaxf(f0 - 12000.0f, 0.0f);
    float b1 = fminf(f1 - 2200.0f, 0.0f);
    float a1 = fmaxf(f1 - r03hi, 0.0f);
    float p = b0 * b0 + a0 * a0 + b1 * b1 + a1 * a1;

    return fmaf(main_t, invB, p);
}

__global__ void __launch_bounds__(THREADS, BLOCKS_PER_SM)
fused_loss_kernel(const float* __restrict__ inputs,
                  const int* __restrict__ targets,
                  const int* __restrict__ cycle_states,
                  const float* __restrict__ weights,
                  float* __restrict__ out,
                  int nrows) {
    // per-warp private pipeline buffers: no cross-warp sharing
    __shared__ __align__(16) unsigned char sbuf[WARPS_PER_BLK][STAGES][STAGE_B];
    __shared__ float w[7];
    __shared__ double sm[WARPS_PER_BLK];
    if (threadIdx.x < 7) w[threadIdx.x] = weights[threadIdx.x];
    __syncthreads();

    const float invB = 1.0f / (float)nrows;
    const int lane   = threadIdx.x & 31;
    const int wid    = threadIdx.x >> 5;
    const int gw     = (int)blockIdx.x * WARPS_PER_BLK + wid;   // global warp id
    const int nwarps = (int)gridDim.x * WARPS_PER_BLK;
    const int nchunk = nrows / CHUNK_ROWS;

    // chunks this warp handles (uniform within warp)
    int mycount = (gw < nchunk) ? (nchunk - gw + nwarps - 1) / nwarps : 0;

    const char* gin = (const char*)inputs;
    const char* gtg = (const char*)targets;
    const char* gcs = (const char*)cycle_states;

    auto issue = [&](int s, int c) {
        unsigned char* sb = sbuf[wid][s];
        size_t c384 = (size_t)c * IN_B;
        size_t c128 = (size_t)c * CS_B;
        if (lane < IN_B / 16) {                         // 24 lanes
            cp16(sb + lane * 16,        gin + c384 + lane * 16);
            cp16(sb + IN_B + lane * 16, gtg + c384 + lane * 16);
        }
        if (lane < CS_B / 16)                           // 8 lanes
            cp16(sb + IN_B + TG_B + lane * 16, gcs + c128 + lane * 16);
    };

    // prologue: exactly STAGES-1 committed groups (pad with empty groups)
    #pragma unroll
    for (int k = 0; k < STAGES - 1; k++) {
        if (k < mycount) issue(k, gw + k * nwarps);
        cp_commit();
    }

    float acc = 0.0f;   // ~22 rows/thread in f32: well within tolerance
    for (int k = 0; k < mycount; k++) {
        cp_wait4();      // oldest group (stage k) landed for THIS thread
        __syncwarp();    // -> landed for ALL lanes; order smem reads

        // refill slot freed last iteration; pad with empty group otherwise
        int c2 = gw + (k + STAGES - 1) * nwarps;
        if (c2 < nchunk) issue((k + STAGES - 1) % STAGES, c2);
        cp_commit();

        const unsigned char* sb = sbuf[wid][k % STAGES];
        const float* s_in = (const float*)sb;
        const int*   s_tg = (const int*)(sb + IN_B);
        const int*   s_cs = (const int*)(sb + IN_B + TG_B);
        float i0 = s_in[3 * lane + 0], i1 = s_in[3 * lane + 1], i2 = s_in[3 * lane + 2];
        int   t0 = s_tg[3 * lane + 0], t1 = s_tg[3 * lane + 1], t2 = s_tg[3 * lane + 2];
        int   cs = s_cs[lane];
        acc += row_term(i0, i1, i2, t0, t1, t2, cs, w, invB);

        __syncwarp();    // consume done before slot reuse next iterations
    }
    cp_wait0();          // drain padding groups

    // tail rows (nrows % 32 != 0; none for B=4M): direct global loads
    int remstart = nchunk * CHUNK_ROWS;
    for (int r = remstart + (int)blockIdx.x * THREADS + (int)threadIdx.x;
         r < nrows; r += (int)gridDim.x * THREADS) {
        acc += row_term(inputs[3 * r], inputs[3 * r + 1], inputs[3 * r + 2],
                        targets[3 * r], targets[3 * r + 1], targets[3 * r + 2],
                        cycle_states[r], w, invB);
    }

    // intra-block reduce in double
    double dacc = (double)acc;
    #pragma unroll
    for (int o = 16; o; o >>= 1)
        dacc += __shfl_down_sync(0xffffffffu, dacc, o);
    if (lane == 0) sm[wid] = dacc;
    __syncthreads();

    __shared__ bool s_last;
    if (threadIdx.x == 0) {
        double v = sm[0];
        #pragma unroll
        for (int i = 1; i < WARPS_PER_BLK; i++) v += sm[i];
        g_part[blockIdx.x] = v;
        __threadfence();
        unsigned int t = atomicAdd(&g_ticket, 1u);
        s_last = (t == gridDim.x - 1);
        if (s_last) g_ticket = 0;   // reset for next graph replay
    }
    __syncthreads();

    // last block reduces all partials and writes the scalar
    if (s_last) {
        __threadfence();
        double v = 0.0;
        for (int i = threadIdx.x; i < (int)gridDim.x; i += THREADS)
            v += g_part[i];
        #pragma unroll
        for (int o = 16; o; o >>= 1)
            v += __shfl_down_sync(0xffffffffu, v, o);
        if (lane == 0) sm[wid] = v;
        __syncthreads();
        if (threadIdx.x == 0) {
            double tot = sm[0];
            #pragma unroll
            for (int i = 1; i < WARPS_PER_BLK; i++) tot += sm[i];
            out[0] = (float)tot;
        }
    }
}

extern "C" void kernel_launch(void* const* d_in, const int* in_sizes, int n_in,
                              void* d_out, int out_size) {
    const float* inputs       = (const float*)d_in[0];   // [B,3] f32
    const int*   targets      = (const int*)d_in[1];     // [B,3] i32
    const int*   cycle_states = (const int*)d_in[2];     // [B]   i32
    const float* weights      = (const float*)d_in[3];   // [7]   f32
    float* out = (float*)d_out;

    int nrows = in_sizes[0] / 3;  // 4,194,304

    int nchunk = nrows / CHUNK_ROWS;
    int blocks = (nchunk + WARPS_PER_BLK - 1) / WARPS_PER_BLK;
    if (blocks > WAVE_BLOCKS) blocks = WAVE_BLOCKS;  // one wave @ 5 blocks/SM
    fused_loss_kernel<<<blocks, THREADS>>>(inputs, targets, cycle_states,
                                           weights, out, nrows);
}